// round 1
// baseline (speedup 1.0000x reference)
#include <cuda_runtime.h>
#include <cstdint>

// Problem constants
#define BB 8
#define TT 2048
#define CC 1024
#define HH 64

// 4 MB scratch for the k projection (q = k = v all use this buffer)
__device__ float g_kbuf[BB * TT * HH];

// ---------------------------------------------------------------------------
// helpers: tf32 convert + m16n8k8 tf32 mma
// ---------------------------------------------------------------------------
__device__ __forceinline__ uint32_t f2t(float x) {
    uint32_t u;
    asm("cvt.rna.tf32.f32 %0, %1;" : "=r"(u) : "f"(x));
    return u;
}

__device__ __forceinline__ void mma8(float* c, const uint32_t* a, const uint32_t* b) {
    asm volatile(
        "mma.sync.aligned.m16n8k8.row.col.f32.tf32.tf32.f32 "
        "{%0,%1,%2,%3}, {%4,%5,%6,%7}, {%8,%9}, {%0,%1,%2,%3};"
        : "+f"(c[0]), "+f"(c[1]), "+f"(c[2]), "+f"(c[3])
        : "r"(a[0]), "r"(a[1]), "r"(a[2]), "r"(a[3]), "r"(b[0]), "r"(b[1]));
}

// ---------------------------------------------------------------------------
// Kernel 1: k = x @ W^T   (x: [B*T, C] fp32, W: [H, C] fp32, k: [B*T, H])
// 128 rows per block, K-chunks of 32, tf32 mma. 256 threads (8 warps, 4m x 2n).
// ---------------------------------------------------------------------------
#define PROJ_M 128
#define PKC 32
#define XS 36   // smem stride for x tile (36 % 32 == 4 -> conflict-free frag loads)
#define WS 36

__global__ __launch_bounds__(256) void proj_kernel(
    const float* __restrict__ x, const float* __restrict__ W, float* __restrict__ ko)
{
    __shared__ float sX[PROJ_M * XS];
    __shared__ float sW[HH * WS];
    const int tid = threadIdx.x;
    const int row0 = blockIdx.x * PROJ_M;
    const int w = tid >> 5, lane = tid & 31, gid = lane >> 2, t4 = lane & 3;
    const int mr0 = 32 * (w & 3);   // 2 m-tiles of 16 rows
    const int n0  = 32 * (w >> 2);  // 4 n-tiles of 8 cols

    float acc[2][4][4];
    #pragma unroll
    for (int i = 0; i < 2; i++)
        #pragma unroll
        for (int j = 0; j < 4; j++)
            #pragma unroll
            for (int l = 0; l < 4; l++) acc[i][j][l] = 0.f;

    for (int c0 = 0; c0 < CC; c0 += PKC) {
        __syncthreads();
        // load x tile 128 x 32 (8 float4 per row)
        #pragma unroll
        for (int i = tid; i < PROJ_M * (PKC / 4); i += 256) {
            int r = i >> 3, c4 = i & 7;
            float4 v = *(const float4*)(x + (size_t)(row0 + r) * CC + c0 + c4 * 4);
            *(float4*)&sX[r * XS + c4 * 4] = v;
        }
        // load W tile 64 x 32
        #pragma unroll
        for (int i = tid; i < HH * (PKC / 4); i += 256) {
            int r = i >> 3, c4 = i & 7;
            float4 v = *(const float4*)(W + (size_t)r * CC + c0 + c4 * 4);
            *(float4*)&sW[r * WS + c4 * 4] = v;
        }
        __syncthreads();

        #pragma unroll
        for (int k0 = 0; k0 < PKC; k0 += 8) {
            uint32_t a[2][4], bb[4][2];
            #pragma unroll
            for (int mt = 0; mt < 2; mt++) {
                const float* p = sX + (mr0 + 16 * mt + gid) * XS + k0 + t4;
                a[mt][0] = f2t(p[0]);
                a[mt][1] = f2t(p[8 * XS]);
                a[mt][2] = f2t(p[4]);
                a[mt][3] = f2t(p[8 * XS + 4]);
            }
            #pragma unroll
            for (int nt = 0; nt < 4; nt++) {
                const float* p = sW + (n0 + 8 * nt + gid) * WS + k0 + t4;
                bb[nt][0] = f2t(p[0]);
                bb[nt][1] = f2t(p[4]);
            }
            #pragma unroll
            for (int mt = 0; mt < 2; mt++)
                #pragma unroll
                for (int nt = 0; nt < 4; nt++) mma8(acc[mt][nt], a[mt], bb[nt]);
        }
    }

    // store C fragments: c0:(gid, 2*t4) c1:(gid, 2*t4+1) c2/c3: row+8
    #pragma unroll
    for (int mt = 0; mt < 2; mt++)
        #pragma unroll
        for (int nt = 0; nt < 4; nt++) {
            int r  = row0 + mr0 + 16 * mt + gid;
            int cc = n0 + 8 * nt + 2 * t4;
            ko[(size_t)r * HH + cc]           = acc[mt][nt][0];
            ko[(size_t)r * HH + cc + 1]       = acc[mt][nt][1];
            ko[(size_t)(r + 8) * HH + cc]     = acc[mt][nt][2];
            ko[(size_t)(r + 8) * HH + cc + 1] = acc[mt][nt][3];
        }
}

// ---------------------------------------------------------------------------
// Kernel 2: causal flash attention with q = k = v = kbuf (scale 1/32 in Q).
// Q tile 64 rows, K tile 128 keys, 256 threads, 2 CTAs/SM.
// ---------------------------------------------------------------------------
#define QT 64
#define KT 128
#define QS 68
#define KS 68
#define SS 132
#define SCALE 0.03125f   // 1024^-0.5

#define ATTN_SMEM_FLOATS (QT * QS + KT * KS + QT * SS + 3 * QT)
#define ATTN_SMEM_BYTES  (ATTN_SMEM_FLOATS * 4)

__global__ __launch_bounds__(256, 2) void attn_kernel(
    const float* __restrict__ kb, float* __restrict__ out)
{
    extern __shared__ float sm[];
    float* sQ = sm;                 // QT*QS
    float* sK = sQ + QT * QS;       // KT*KS
    float* sS = sK + KT * KS;       // QT*SS
    float* sM = sS + QT * SS;       // QT
    float* sL = sM + QT;            // QT
    float* sA = sL + QT;            // QT

    const int tid = threadIdx.x;
    const int qt = (int)(gridDim.x - 1 - blockIdx.x);  // longest blocks first
    const int b = blockIdx.y;
    const int qrow0 = qt * QT;
    const float* kbase = kb + (size_t)b * TT * HH;

    const int w = tid >> 5, lane = tid & 31, gid = lane >> 2, t4 = lane & 3;

    // load Q tile (scaled)
    #pragma unroll
    for (int i = tid; i < QT * (HH / 4); i += 256) {
        int r = i >> 4, c4 = i & 15;
        float4 v = *(const float4*)(kbase + (size_t)(qrow0 + r) * HH + c4 * 4);
        v.x *= SCALE; v.y *= SCALE; v.z *= SCALE; v.w *= SCALE;
        *(float4*)&sQ[r * QS + c4 * 4] = v;
    }
    if (tid < QT) { sM[tid] = -1e30f; sL[tid] = 0.f; }

    // PV / O partition: 4m x 2n (16 rows x 32 cols per warp)
    const int mw = w & 3, nh = w >> 2;
    float o[4][4];
    #pragma unroll
    for (int i = 0; i < 4; i++)
        #pragma unroll
        for (int j = 0; j < 4; j++) o[i][j] = 0.f;

    // QK partition: 2m x 4n (32 rows x 32 cols per warp)
    const int qmr0 = 32 * (w & 1), qn0 = 32 * (w >> 1);

    const int jmax = (qrow0 + QT - 1) >> 7;
    for (int j = 0; j <= jmax; j++) {
        __syncthreads();  // prior PV done reading sK/sS
        // load K tile (also used as V)
        #pragma unroll
        for (int i = tid; i < KT * (HH / 4); i += 256) {
            int r = i >> 4, c4 = i & 15;
            *(float4*)&sK[r * KS + c4 * 4] =
                *(const float4*)(kbase + (size_t)(j * KT + r) * HH + c4 * 4);
        }
        __syncthreads();

        // ---- S = Q K^T (tf32 mma), write to sS ----
        float s[2][4][4];
        #pragma unroll
        for (int i = 0; i < 2; i++)
            #pragma unroll
            for (int jj = 0; jj < 4; jj++)
                #pragma unroll
                for (int l = 0; l < 4; l++) s[i][jj][l] = 0.f;

        #pragma unroll
        for (int k0 = 0; k0 < HH; k0 += 8) {
            uint32_t a[2][4], bbf[4][2];
            #pragma unroll
            for (int mt = 0; mt < 2; mt++) {
                const float* p = sQ + (qmr0 + 16 * mt + gid) * QS + k0 + t4;
                a[mt][0] = f2t(p[0]);
                a[mt][1] = f2t(p[8 * QS]);
                a[mt][2] = f2t(p[4]);
                a[mt][3] = f2t(p[8 * QS + 4]);
            }
            #pragma unroll
            for (int nt = 0; nt < 4; nt++) {
                const float* p = sK + (qn0 + 8 * nt + gid) * KS + k0 + t4;
                bbf[nt][0] = f2t(p[0]);
                bbf[nt][1] = f2t(p[4]);
            }
            #pragma unroll
            for (int mt = 0; mt < 2; mt++)
                #pragma unroll
                for (int nt = 0; nt < 4; nt++) mma8(s[mt][nt], a[mt], bbf[nt]);
        }
        #pragma unroll
        for (int mt = 0; mt < 2; mt++)
            #pragma unroll
            for (int nt = 0; nt < 4; nt++) {
                int r  = qmr0 + 16 * mt + gid;
                int cc = qn0 + 8 * nt + 2 * t4;
                sS[r * SS + cc]           = s[mt][nt][0];
                sS[r * SS + cc + 1]       = s[mt][nt][1];
                sS[(r + 8) * SS + cc]     = s[mt][nt][2];
                sS[(r + 8) * SS + cc + 1] = s[mt][nt][3];
            }
        __syncthreads();

        // ---- online softmax: 4 threads per row, 32 cols each ----
        {
            int r = tid >> 2, q = tid & 3;
            int tg = qrow0 + r;
            int nvalid = tg - j * KT - 32 * q + 1;  // cc < nvalid is unmasked
            float* Srow = sS + r * SS + 32 * q;
            float mloc = -1e30f;
            #pragma unroll
            for (int c4 = 0; c4 < 8; c4++) {
                float4 v = *(float4*)&Srow[c4 * 4];
                int cb = c4 * 4;
                if (cb + 0 < nvalid) mloc = fmaxf(mloc, v.x);
                if (cb + 1 < nvalid) mloc = fmaxf(mloc, v.y);
                if (cb + 2 < nvalid) mloc = fmaxf(mloc, v.z);
                if (cb + 3 < nvalid) mloc = fmaxf(mloc, v.w);
            }
            mloc = fmaxf(mloc, __shfl_xor_sync(0xffffffffu, mloc, 1));
            mloc = fmaxf(mloc, __shfl_xor_sync(0xffffffffu, mloc, 2));
            float mold = sM[r];
            float mnew = fmaxf(mold, mloc);
            float alpha = __expf(mold - mnew);
            float sum = 0.f;
            #pragma unroll
            for (int c4 = 0; c4 < 8; c4++) {
                float4 v = *(float4*)&Srow[c4 * 4];
                int cb = c4 * 4;
                v.x = (cb + 0 < nvalid) ? __expf(v.x - mnew) : 0.f;
                v.y = (cb + 1 < nvalid) ? __expf(v.y - mnew) : 0.f;
                v.z = (cb + 2 < nvalid) ? __expf(v.z - mnew) : 0.f;
                v.w = (cb + 3 < nvalid) ? __expf(v.w - mnew) : 0.f;
                sum += v.x + v.y + v.z + v.w;
                *(float4*)&Srow[c4 * 4] = v;
            }
            sum += __shfl_xor_sync(0xffffffffu, sum, 1);
            sum += __shfl_xor_sync(0xffffffffu, sum, 2);
            if (q == 0) { sM[r] = mnew; sL[r] = sL[r] * alpha + sum; sA[r] = alpha; }
        }
        __syncthreads();

        // ---- rescale O, then O += P V (tf32 mma from smem) ----
        float a1 = sA[16 * mw + gid], a2 = sA[16 * mw + gid + 8];
        #pragma unroll
        for (int nt = 0; nt < 4; nt++) {
            o[nt][0] *= a1; o[nt][1] *= a1; o[nt][2] *= a2; o[nt][3] *= a2;
        }
        #pragma unroll
        for (int k0 = 0; k0 < KT; k0 += 8) {
            uint32_t a[4];
            const float* p = sS + (16 * mw + gid) * SS + k0 + t4;
            a[0] = f2t(p[0]);
            a[1] = f2t(p[8 * SS]);
            a[2] = f2t(p[4]);
            a[3] = f2t(p[8 * SS + 4]);
            #pragma unroll
            for (int nt = 0; nt < 4; nt++) {
                uint32_t bbf[2];
                const float* pv = sK + (k0 + t4) * KS + 32 * nh + 8 * nt + gid;
                bbf[0] = f2t(pv[0]);
                bbf[1] = f2t(pv[4 * KS]);
                mma8(o[nt], a, bbf);
            }
        }
    }

    // epilogue: out = O / l
    float il1 = 1.f / sL[16 * mw + gid];
    float il2 = 1.f / sL[16 * mw + gid + 8];
    float* ob = out + (size_t)b * TT * HH;
    #pragma unroll
    for (int nt = 0; nt < 4; nt++) {
        int r  = qrow0 + 16 * mw + gid;
        int cc = 32 * nh + 8 * nt + 2 * t4;
        ob[(size_t)r * HH + cc]           = o[nt][0] * il1;
        ob[(size_t)r * HH + cc + 1]       = o[nt][1] * il1;
        ob[(size_t)(r + 8) * HH + cc]     = o[nt][2] * il2;
        ob[(size_t)(r + 8) * HH + cc + 1] = o[nt][3] * il2;
    }
}

// ---------------------------------------------------------------------------
// launch
// ---------------------------------------------------------------------------
extern "C" void kernel_launch(void* const* d_in, const int* in_sizes, int n_in,
                              void* d_out, int out_size)
{
    const float* x = (const float*)d_in[0];   // [B, T, C]
    const float* W = (const float*)d_in[1];   // [H, C]
    float* out = (float*)d_out;               // [B, T, H]

    float* kbuf = nullptr;
    cudaGetSymbolAddress((void**)&kbuf, g_kbuf);

    cudaFuncSetAttribute(attn_kernel, cudaFuncAttributeMaxDynamicSharedMemorySize,
                         ATTN_SMEM_BYTES);

    proj_kernel<<<(BB * TT) / PROJ_M, 256>>>(x, W, kbuf);

    dim3 g(TT / QT, BB);
    attn_kernel<<<g, 256, ATTN_SMEM_BYTES>>>(kbuf, out);
}

// round 2
// speedup vs baseline: 1.5357x; 1.5357x over previous
#include <cuda_runtime.h>
#include <cstdint>

// Problem constants
#define BB 8
#define TT 2048
#define CC 1024
#define HH 64

// 4 MB scratch for the k projection (q = k = v all use this buffer), tf32-rounded bits
__device__ float g_kbuf[BB * TT * HH];

// ---------------------------------------------------------------------------
// helpers
// ---------------------------------------------------------------------------
__device__ __forceinline__ uint32_t f2t(float x) {
    uint32_t u;
    asm("cvt.rna.tf32.f32 %0, %1;" : "=r"(u) : "f"(x));
    return u;
}

__device__ __forceinline__ void mma8(float* c, const uint32_t* a, const uint32_t* b) {
    asm volatile(
        "mma.sync.aligned.m16n8k8.row.col.f32.tf32.tf32.f32 "
        "{%0,%1,%2,%3}, {%4,%5,%6,%7}, {%8,%9}, {%0,%1,%2,%3};"
        : "+f"(c[0]), "+f"(c[1]), "+f"(c[2]), "+f"(c[3])
        : "r"(a[0]), "r"(a[1]), "r"(a[2]), "r"(a[3]), "r"(b[0]), "r"(b[1]));
}

// ---------------------------------------------------------------------------
// Kernel 1: k = tf32(x @ W^T)  (x: [B*T, C], W: [H, C], k: [B*T, H])
// 64 rows/block (256 blocks), 256 threads, register-staged double buffering.
// ---------------------------------------------------------------------------
#define PROJ_M 64
#define PKC 32
#define XS 36
#define WS 36

__global__ __launch_bounds__(256) void proj_kernel(
    const float* __restrict__ x, const float* __restrict__ W, float* __restrict__ ko)
{
    __shared__ float sX[PROJ_M * XS];
    __shared__ float sW[HH * WS];
    const int tid = threadIdx.x;
    const int row0 = blockIdx.x * PROJ_M;
    const int w = tid >> 5, lane = tid & 31, gid = lane >> 2, t4 = lane & 3;
    const int mw = w & 3;       // 4 row-groups of 16
    const int nh = w >> 2;      // 2 col-groups of 32 (4 n-tiles each)

    float acc[4][4];
    #pragma unroll
    for (int i = 0; i < 4; i++)
        #pragma unroll
        for (int l = 0; l < 4; l++) acc[i][l] = 0.f;

    // register stage: 2 x-float4 + 2 W-float4 per thread per chunk
    float4 stx[2], stw[2];
    #pragma unroll
    for (int t = 0; t < 2; t++) {
        int i = tid + 256 * t;
        int r = i >> 3, c4 = i & 7;
        stx[t] = *(const float4*)(x + (size_t)(row0 + r) * CC + c4 * 4);
        stw[t] = *(const float4*)(W + (size_t)r * CC + c4 * 4);
    }

    for (int c0 = 0; c0 < CC; c0 += PKC) {
        __syncthreads();
        #pragma unroll
        for (int t = 0; t < 2; t++) {
            int i = tid + 256 * t;
            int r = i >> 3, c4 = i & 7;
            *(float4*)&sX[r * XS + c4 * 4] = stx[t];
            *(float4*)&sW[r * WS + c4 * 4] = stw[t];
        }
        __syncthreads();
        if (c0 + PKC < CC) {
            #pragma unroll
            for (int t = 0; t < 2; t++) {
                int i = tid + 256 * t;
                int r = i >> 3, c4 = i & 7;
                stx[t] = *(const float4*)(x + (size_t)(row0 + r) * CC + c0 + PKC + c4 * 4);
                stw[t] = *(const float4*)(W + (size_t)r * CC + c0 + PKC + c4 * 4);
            }
        }
        #pragma unroll
        for (int k0 = 0; k0 < PKC; k0 += 8) {
            uint32_t a[4];
            const float* pq = sX + (16 * mw + gid) * XS + k0 + t4;
            a[0] = f2t(pq[0]);
            a[1] = f2t(pq[8 * XS]);
            a[2] = f2t(pq[4]);
            a[3] = f2t(pq[8 * XS + 4]);
            #pragma unroll
            for (int nt = 0; nt < 4; nt++) {
                const float* pw = sW + (32 * nh + 8 * nt + gid) * WS + k0 + t4;
                uint32_t bb[2] = { f2t(pw[0]), f2t(pw[4]) };
                mma8(acc[nt], a, bb);
            }
        }
    }

    // epilogue: store tf32-rounded bit patterns
    #pragma unroll
    for (int nt = 0; nt < 4; nt++) {
        int r = row0 + 16 * mw + gid;
        int c = 32 * nh + 8 * nt + 2 * t4;
        ko[(size_t)r * HH + c]           = __uint_as_float(f2t(acc[nt][0]));
        ko[(size_t)r * HH + c + 1]       = __uint_as_float(f2t(acc[nt][1]));
        ko[(size_t)(r + 8) * HH + c]     = __uint_as_float(f2t(acc[nt][2]));
        ko[(size_t)(r + 8) * HH + c + 1] = __uint_as_float(f2t(acc[nt][3]));
    }
}

// ---------------------------------------------------------------------------
// Kernel 2: causal flash attention, q = k = v = kbuf (tf32 bits), scale 1/32.
// 128 threads (4 warps). Each warp owns 16 q-rows x all 128 key-cols.
// Softmax fully in registers (quad shuffles); P never hits SMEM.
// ---------------------------------------------------------------------------
#define QT 64
#define KT 128
#define QS 68
#define KS 68
#define SCALE 0.03125f   // 1024^-0.5 = 2^-5 (exact on tf32)

#define ATTN_SMEM_FLOATS (QT * QS + KT * KS)
#define ATTN_SMEM_BYTES  (ATTN_SMEM_FLOATS * 4)

__global__ __launch_bounds__(128, 3) void attn_kernel(
    const float* __restrict__ kb, float* __restrict__ out)
{
    extern __shared__ float sm[];
    float* sQ = sm;             // QT*QS
    float* sK = sQ + QT * QS;   // KT*KS

    const int tid = threadIdx.x;
    const int qt = (int)(gridDim.x - 1 - blockIdx.x);  // longest blocks first
    const int b = blockIdx.y;
    const int qrow0 = qt * QT;
    const float* kbase = kb + (size_t)b * TT * HH;

    const int w = tid >> 5, lane = tid & 31, gid = lane >> 2, t4 = lane & 3;
    const int srcA = (lane & ~3) | (t4 >> 1);
    const int srcB = srcA + 2;
    const bool odd = (t4 & 1);

    // load Q tile (scaled; stays tf32-representable)
    #pragma unroll
    for (int i = tid; i < QT * (HH / 4); i += 128) {
        int r = i >> 4, c4 = i & 15;
        float4 v = *(const float4*)(kbase + (size_t)(qrow0 + r) * HH + c4 * 4);
        v.x *= SCALE; v.y *= SCALE; v.z *= SCALE; v.w *= SCALE;
        *(float4*)&sQ[r * QS + c4 * 4] = v;
    }

    // per-thread softmax state for rows (16w+gid) and (16w+gid+8)
    float m0 = -1e30f, m1 = -1e30f, l0 = 0.f, l1 = 0.f;
    const int rg0 = qrow0 + 16 * w + gid;
    const int rg1 = rg0 + 8;

    float o[8][4];
    #pragma unroll
    for (int i = 0; i < 8; i++)
        #pragma unroll
        for (int l = 0; l < 4; l++) o[i][l] = 0.f;

    const int jmax = (qrow0 + QT - 1) >> 7;
    for (int j = 0; j <= jmax; j++) {
        __syncthreads();  // previous PV done reading sK
        #pragma unroll
        for (int i = tid; i < KT * (HH / 4); i += 128) {
            int r = i >> 4, c4 = i & 15;
            *(float4*)&sK[r * KS + c4 * 4] =
                *(const float4*)(kbase + (size_t)(j * KT + r) * HH + c4 * 4);
        }
        __syncthreads();

        // ---- S = Q K^T : warp computes 16 rows x 128 cols, c-frags s[16][4] ----
        float s[16][4];
        #pragma unroll
        for (int nt = 0; nt < 16; nt++)
            #pragma unroll
            for (int l = 0; l < 4; l++) s[nt][l] = 0.f;

        #pragma unroll
        for (int k0 = 0; k0 < HH; k0 += 8) {
            uint32_t a[4];
            const float* pq = sQ + (16 * w + gid) * QS + k0 + t4;
            a[0] = __float_as_uint(pq[0]);
            a[1] = __float_as_uint(pq[8 * QS]);
            a[2] = __float_as_uint(pq[4]);
            a[3] = __float_as_uint(pq[8 * QS + 4]);
            #pragma unroll
            for (int nt = 0; nt < 16; nt++) {
                const float* pk = sK + (8 * nt + gid) * KS + k0 + t4;
                uint32_t bb[2] = { __float_as_uint(pk[0]), __float_as_uint(pk[4]) };
                mma8(s[nt], a, bb);
            }
        }

        // ---- causal mask (only the diagonal tile needs it) ----
        if (j == jmax) {
            #pragma unroll
            for (int nt = 0; nt < 16; nt++) {
                int kc = j * KT + 8 * nt + 2 * t4;
                if (kc     > rg0) s[nt][0] = -1e30f;
                if (kc + 1 > rg0) s[nt][1] = -1e30f;
                if (kc     > rg1) s[nt][2] = -1e30f;
                if (kc + 1 > rg1) s[nt][3] = -1e30f;
            }
        }

        // ---- online softmax in registers ----
        float mx0 = -1e30f, mx1 = -1e30f;
        #pragma unroll
        for (int nt = 0; nt < 16; nt++) {
            mx0 = fmaxf(mx0, fmaxf(s[nt][0], s[nt][1]));
            mx1 = fmaxf(mx1, fmaxf(s[nt][2], s[nt][3]));
        }
        mx0 = fmaxf(mx0, __shfl_xor_sync(0xffffffffu, mx0, 1));
        mx0 = fmaxf(mx0, __shfl_xor_sync(0xffffffffu, mx0, 2));
        mx1 = fmaxf(mx1, __shfl_xor_sync(0xffffffffu, mx1, 1));
        mx1 = fmaxf(mx1, __shfl_xor_sync(0xffffffffu, mx1, 2));

        float mn0 = fmaxf(m0, mx0), mn1 = fmaxf(m1, mx1);
        float al0 = __expf(m0 - mn0), al1 = __expf(m1 - mn1);
        m0 = mn0; m1 = mn1;

        float sum0 = 0.f, sum1 = 0.f;
        #pragma unroll
        for (int nt = 0; nt < 16; nt++) {
            s[nt][0] = __expf(s[nt][0] - mn0);
            s[nt][1] = __expf(s[nt][1] - mn0);
            s[nt][2] = __expf(s[nt][2] - mn1);
            s[nt][3] = __expf(s[nt][3] - mn1);
            sum0 += s[nt][0] + s[nt][1];
            sum1 += s[nt][2] + s[nt][3];
        }
        sum0 += __shfl_xor_sync(0xffffffffu, sum0, 1);
        sum0 += __shfl_xor_sync(0xffffffffu, sum0, 2);
        sum1 += __shfl_xor_sync(0xffffffffu, sum1, 1);
        sum1 += __shfl_xor_sync(0xffffffffu, sum1, 2);
        l0 = l0 * al0 + sum0;
        l1 = l1 * al1 + sum1;

        // ---- rescale O ----
        #pragma unroll
        for (int nt = 0; nt < 8; nt++) {
            o[nt][0] *= al0; o[nt][1] *= al0; o[nt][2] *= al1; o[nt][3] *= al1;
        }

        // ---- O += P V : a-frags from c-frags via quad shuffles ----
        #pragma unroll
        for (int kk = 0; kk < 16; kk++) {
            float v00 = __shfl_sync(0xffffffffu, s[kk][0], srcA);
            float v01 = __shfl_sync(0xffffffffu, s[kk][1], srcA);
            float v10 = __shfl_sync(0xffffffffu, s[kk][0], srcB);
            float v11 = __shfl_sync(0xffffffffu, s[kk][1], srcB);
            float v20 = __shfl_sync(0xffffffffu, s[kk][2], srcA);
            float v21 = __shfl_sync(0xffffffffu, s[kk][3], srcA);
            float v30 = __shfl_sync(0xffffffffu, s[kk][2], srcB);
            float v31 = __shfl_sync(0xffffffffu, s[kk][3], srcB);
            uint32_t a[4];
            a[0] = f2t(odd ? v01 : v00);  // (row gid,   k=t4)
            a[1] = f2t(odd ? v21 : v20);  // (row gid+8, k=t4)
            a[2] = f2t(odd ? v11 : v10);  // (row gid,   k=t4+4)
            a[3] = f2t(odd ? v31 : v30);  // (row gid+8, k=t4+4)
            #pragma unroll
            for (int nt = 0; nt < 8; nt++) {
                const float* pv = sK + (8 * kk + t4) * KS + 8 * nt + gid;
                uint32_t bb[2] = { __float_as_uint(pv[0]), __float_as_uint(pv[4 * KS]) };
                mma8(o[nt], a, bb);
            }
        }
    }

    // ---- epilogue ----
    float il0 = 1.f / l0, il1 = 1.f / l1;
    float* ob = out + (size_t)b * TT * HH;
    #pragma unroll
    for (int nt = 0; nt < 8; nt++) {
        int c = 8 * nt + 2 * t4;
        float2 r0v = { o[nt][0] * il0, o[nt][1] * il0 };
        float2 r1v = { o[nt][2] * il1, o[nt][3] * il1 };
        *(float2*)(ob + (size_t)rg0 * HH + c) = r0v;
        *(float2*)(ob + (size_t)rg1 * HH + c) = r1v;
    }
}

// ---------------------------------------------------------------------------
// launch
// ---------------------------------------------------------------------------
extern "C" void kernel_launch(void* const* d_in, const int* in_sizes, int n_in,
                              void* d_out, int out_size)
{
    const float* x = (const float*)d_in[0];   // [B, T, C]
    const float* W = (const float*)d_in[1];   // [H, C]
    float* out = (float*)d_out;               // [B, T, H]

    float* kbuf = nullptr;
    cudaGetSymbolAddress((void**)&kbuf, g_kbuf);

    cudaFuncSetAttribute(attn_kernel, cudaFuncAttributeMaxDynamicSharedMemorySize,
                         ATTN_SMEM_BYTES);

    proj_kernel<<<(BB * TT) / PROJ_M, 256>>>(x, W, kbuf);

    dim3 g(TT / QT, BB);
    attn_kernel<<<g, 128, ATTN_SMEM_BYTES>>>(kbuf, out);
}

// round 3
// speedup vs baseline: 1.7501x; 1.1396x over previous
#include <cuda_runtime.h>
#include <cstdint>

// Problem constants
#define BB 8
#define TT 2048
#define CC 1024
#define HH 64

// k projection scratch (q = k = v), tf32-rounded bit patterns
__device__ float g_kbuf[BB * TT * HH];
// KV-split partials: 256 tiles x 64 rows x 64 cols (unnormalized O)
__device__ float g_part[256 * 64 * 64];
// per-row (m, l) for each partial tile
__device__ float g_stats[256 * 64 * 2];

// ---------------------------------------------------------------------------
// helpers
// ---------------------------------------------------------------------------
__device__ __forceinline__ uint32_t f2t(float x) {
    uint32_t u;
    asm("cvt.rna.tf32.f32 %0, %1;" : "=r"(u) : "f"(x));
    return u;
}

__device__ __forceinline__ void mma8(float* c, const uint32_t* a, const uint32_t* b) {
    asm volatile(
        "mma.sync.aligned.m16n8k8.row.col.f32.tf32.tf32.f32 "
        "{%0,%1,%2,%3}, {%4,%5,%6,%7}, {%8,%9}, {%0,%1,%2,%3};"
        : "+f"(c[0]), "+f"(c[1]), "+f"(c[2]), "+f"(c[3])
        : "r"(a[0]), "r"(a[1]), "r"(a[2]), "r"(a[3]), "r"(b[0]), "r"(b[1]));
}

// ---------------------------------------------------------------------------
// Kernel 1: k = tf32(x @ W^T). 64 rows/block, K-chunks of 64, reg-staged
// double buffering. 256 threads (8 warps, 4m x 2n).
// ---------------------------------------------------------------------------
#define PROJ_M 64
#define PKC 64
#define XS 68
#define WS 68

__global__ __launch_bounds__(256) void proj_kernel(
    const float* __restrict__ x, const float* __restrict__ W, float* __restrict__ ko)
{
    __shared__ float sX[PROJ_M * XS];
    __shared__ float sW[HH * WS];
    const int tid = threadIdx.x;
    const int row0 = blockIdx.x * PROJ_M;
    const int w = tid >> 5, lane = tid & 31, gid = lane >> 2, t4 = lane & 3;
    const int mw = w & 3;
    const int nh = w >> 2;

    float acc[4][4];
    #pragma unroll
    for (int i = 0; i < 4; i++)
        #pragma unroll
        for (int l = 0; l < 4; l++) acc[i][l] = 0.f;

    float4 stx[4], stw[4];
    #pragma unroll
    for (int t = 0; t < 4; t++) {
        int i = tid + 256 * t;
        int r = i >> 4, c4 = i & 15;
        stx[t] = *(const float4*)(x + (size_t)(row0 + r) * CC + c4 * 4);
        stw[t] = *(const float4*)(W + (size_t)r * CC + c4 * 4);
    }

    for (int c0 = 0; c0 < CC; c0 += PKC) {
        __syncthreads();
        #pragma unroll
        for (int t = 0; t < 4; t++) {
            int i = tid + 256 * t;
            int r = i >> 4, c4 = i & 15;
            *(float4*)&sX[r * XS + c4 * 4] = stx[t];
            *(float4*)&sW[r * WS + c4 * 4] = stw[t];
        }
        __syncthreads();
        if (c0 + PKC < CC) {
            #pragma unroll
            for (int t = 0; t < 4; t++) {
                int i = tid + 256 * t;
                int r = i >> 4, c4 = i & 15;
                stx[t] = *(const float4*)(x + (size_t)(row0 + r) * CC + c0 + PKC + c4 * 4);
                stw[t] = *(const float4*)(W + (size_t)r * CC + c0 + PKC + c4 * 4);
            }
        }
        #pragma unroll
        for (int k0 = 0; k0 < PKC; k0 += 8) {
            uint32_t a[4];
            const float* pq = sX + (16 * mw + gid) * XS + k0 + t4;
            a[0] = f2t(pq[0]);
            a[1] = f2t(pq[8 * XS]);
            a[2] = f2t(pq[4]);
            a[3] = f2t(pq[8 * XS + 4]);
            #pragma unroll
            for (int nt = 0; nt < 4; nt++) {
                const float* pw = sW + (32 * nh + 8 * nt + gid) * WS + k0 + t4;
                uint32_t bb[2] = { f2t(pw[0]), f2t(pw[4]) };
                mma8(acc[nt], a, bb);
            }
        }
    }

    #pragma unroll
    for (int nt = 0; nt < 4; nt++) {
        int r = row0 + 16 * mw + gid;
        int c = 32 * nh + 8 * nt + 2 * t4;
        ko[(size_t)r * HH + c]           = __uint_as_float(f2t(acc[nt][0]));
        ko[(size_t)r * HH + c + 1]       = __uint_as_float(f2t(acc[nt][1]));
        ko[(size_t)(r + 8) * HH + c]     = __uint_as_float(f2t(acc[nt][2]));
        ko[(size_t)(r + 8) * HH + c + 1] = __uint_as_float(f2t(acc[nt][3]));
    }
}

// ---------------------------------------------------------------------------
// Kernel 2: causal flash attention with KV-split.
// Work items per batch: items 0..31 -> split halves of q-tiles 16..31;
// items 32..47 -> q-tiles 0..15 unsplit. Every item runs <= 8 key-tile iters,
// so all 384 blocks fit in one wave with a balanced critical path.
// ---------------------------------------------------------------------------
#define QT 64
#define KT 128
#define QS 68
#define KS 68
#define SCALE 0.03125f   // 1024^-0.5 = 2^-5 (exact on tf32)

#define ATTN_SMEM_FLOATS (QT * QS + KT * KS)
#define ATTN_SMEM_BYTES  (ATTN_SMEM_FLOATS * 4)

__global__ __launch_bounds__(128, 3) void attn_kernel(
    const float* __restrict__ kb, float* __restrict__ out,
    float* __restrict__ part, float* __restrict__ stats)
{
    extern __shared__ float sm[];
    float* sQ = sm;             // QT*QS
    float* sK = sQ + QT * QS;   // KT*KS

    const int tid = threadIdx.x;
    const int item = blockIdx.x;
    const int b = blockIdx.y;

    int qt, j0, j1, split;
    bool is_split;
    if (item < 32) {
        qt = 16 + (item >> 1);
        split = item & 1;
        int jm = qt >> 1;          // global diagonal tile index
        int h = (jm + 1) >> 1;     // split point
        if (split == 0) { j0 = 0; j1 = h - 1; }
        else            { j0 = h; j1 = jm; }
        is_split = true;
    } else {
        qt = item - 32;
        split = 0;
        j0 = 0; j1 = qt >> 1;
        is_split = false;
    }
    const int jmaskg = qt >> 1;    // tile needing the causal mask
    const int qrow0 = qt * QT;
    const float* kbase = kb + (size_t)b * TT * HH;

    const int w = tid >> 5, lane = tid & 31, gid = lane >> 2, t4 = lane & 3;
    const int srcA = (lane & ~3) | (t4 >> 1);
    const int srcB = srcA + 2;
    const bool odd = (t4 & 1);

    // load Q tile (scaled; exact power-of-two scale keeps tf32 bits)
    #pragma unroll
    for (int i = tid; i < QT * (HH / 4); i += 128) {
        int r = i >> 4, c4 = i & 15;
        float4 v = *(const float4*)(kbase + (size_t)(qrow0 + r) * HH + c4 * 4);
        v.x *= SCALE; v.y *= SCALE; v.z *= SCALE; v.w *= SCALE;
        *(float4*)&sQ[r * QS + c4 * 4] = v;
    }

    float m0 = -1e30f, m1 = -1e30f, l0 = 0.f, l1 = 0.f;
    const int rg0 = qrow0 + 16 * w + gid;
    const int rg1 = rg0 + 8;

    float o[8][4];
    #pragma unroll
    for (int i = 0; i < 8; i++)
        #pragma unroll
        for (int l = 0; l < 4; l++) o[i][l] = 0.f;

    for (int j = j0; j <= j1; j++) {
        __syncthreads();
        #pragma unroll
        for (int i = tid; i < KT * (HH / 4); i += 128) {
            int r = i >> 4, c4 = i & 15;
            *(float4*)&sK[r * KS + c4 * 4] =
                *(const float4*)(kbase + (size_t)(j * KT + r) * HH + c4 * 4);
        }
        __syncthreads();

        // ---- S = Q K^T ----
        float s[16][4];
        #pragma unroll
        for (int nt = 0; nt < 16; nt++)
            #pragma unroll
            for (int l = 0; l < 4; l++) s[nt][l] = 0.f;

        #pragma unroll
        for (int k0 = 0; k0 < HH; k0 += 8) {
            uint32_t a[4];
            const float* pq = sQ + (16 * w + gid) * QS + k0 + t4;
            a[0] = __float_as_uint(pq[0]);
            a[1] = __float_as_uint(pq[8 * QS]);
            a[2] = __float_as_uint(pq[4]);
            a[3] = __float_as_uint(pq[8 * QS + 4]);
            #pragma unroll
            for (int nt = 0; nt < 16; nt++) {
                const float* pk = sK + (8 * nt + gid) * KS + k0 + t4;
                uint32_t bb[2] = { __float_as_uint(pk[0]), __float_as_uint(pk[4]) };
                mma8(s[nt], a, bb);
            }
        }

        // ---- causal mask (diagonal tile only) ----
        if (j == jmaskg) {
            #pragma unroll
            for (int nt = 0; nt < 16; nt++) {
                int kc = j * KT + 8 * nt + 2 * t4;
                if (kc     > rg0) s[nt][0] = -1e30f;
                if (kc + 1 > rg0) s[nt][1] = -1e30f;
                if (kc     > rg1) s[nt][2] = -1e30f;
                if (kc + 1 > rg1) s[nt][3] = -1e30f;
            }
        }

        // ---- online softmax in registers ----
        float mx0 = -1e30f, mx1 = -1e30f;
        #pragma unroll
        for (int nt = 0; nt < 16; nt++) {
            mx0 = fmaxf(mx0, fmaxf(s[nt][0], s[nt][1]));
            mx1 = fmaxf(mx1, fmaxf(s[nt][2], s[nt][3]));
        }
        mx0 = fmaxf(mx0, __shfl_xor_sync(0xffffffffu, mx0, 1));
        mx0 = fmaxf(mx0, __shfl_xor_sync(0xffffffffu, mx0, 2));
        mx1 = fmaxf(mx1, __shfl_xor_sync(0xffffffffu, mx1, 1));
        mx1 = fmaxf(mx1, __shfl_xor_sync(0xffffffffu, mx1, 2));

        float mn0 = fmaxf(m0, mx0), mn1 = fmaxf(m1, mx1);
        float al0 = __expf(m0 - mn0), al1 = __expf(m1 - mn1);
        m0 = mn0; m1 = mn1;

        float sum0 = 0.f, sum1 = 0.f;
        #pragma unroll
        for (int nt = 0; nt < 16; nt++) {
            s[nt][0] = __expf(s[nt][0] - mn0);
            s[nt][1] = __expf(s[nt][1] - mn0);
            s[nt][2] = __expf(s[nt][2] - mn1);
            s[nt][3] = __expf(s[nt][3] - mn1);
            sum0 += s[nt][0] + s[nt][1];
            sum1 += s[nt][2] + s[nt][3];
        }
        sum0 += __shfl_xor_sync(0xffffffffu, sum0, 1);
        sum0 += __shfl_xor_sync(0xffffffffu, sum0, 2);
        sum1 += __shfl_xor_sync(0xffffffffu, sum1, 1);
        sum1 += __shfl_xor_sync(0xffffffffu, sum1, 2);
        l0 = l0 * al0 + sum0;
        l1 = l1 * al1 + sum1;

        #pragma unroll
        for (int nt = 0; nt < 8; nt++) {
            o[nt][0] *= al0; o[nt][1] *= al0; o[nt][2] *= al1; o[nt][3] *= al1;
        }

        // ---- O += P V : a-frags from c-frags via quad shuffles ----
        #pragma unroll
        for (int kk = 0; kk < 16; kk++) {
            float v00 = __shfl_sync(0xffffffffu, s[kk][0], srcA);
            float v01 = __shfl_sync(0xffffffffu, s[kk][1], srcA);
            float v10 = __shfl_sync(0xffffffffu, s[kk][0], srcB);
            float v11 = __shfl_sync(0xffffffffu, s[kk][1], srcB);
            float v20 = __shfl_sync(0xffffffffu, s[kk][2], srcA);
            float v21 = __shfl_sync(0xffffffffu, s[kk][3], srcA);
            float v30 = __shfl_sync(0xffffffffu, s[kk][2], srcB);
            float v31 = __shfl_sync(0xffffffffu, s[kk][3], srcB);
            uint32_t a[4];
            a[0] = f2t(odd ? v01 : v00);
            a[1] = f2t(odd ? v21 : v20);
            a[2] = f2t(odd ? v11 : v10);
            a[3] = f2t(odd ? v31 : v30);
            #pragma unroll
            for (int nt = 0; nt < 8; nt++) {
                const float* pv = sK + (8 * kk + t4) * KS + 8 * nt + gid;
                uint32_t bb[2] = { __float_as_uint(pv[0]), __float_as_uint(pv[4 * KS]) };
                mma8(o[nt], a, bb);
            }
        }
    }

    if (!is_split) {
        float il0 = 1.f / l0, il1 = 1.f / l1;
        float* ob = out + (size_t)b * TT * HH;
        #pragma unroll
        for (int nt = 0; nt < 8; nt++) {
            int c = 8 * nt + 2 * t4;
            float2 r0v = { o[nt][0] * il0, o[nt][1] * il0 };
            float2 r1v = { o[nt][2] * il1, o[nt][3] * il1 };
            *(float2*)(ob + (size_t)rg0 * HH + c) = r0v;
            *(float2*)(ob + (size_t)rg1 * HH + c) = r1v;
        }
    } else {
        const int part_id = (b * 16 + (qt - 16)) * 2 + split;
        float* po = part + (size_t)part_id * (QT * HH);
        const int lr0 = 16 * w + gid, lr1 = lr0 + 8;
        #pragma unroll
        for (int nt = 0; nt < 8; nt++) {
            int c = 8 * nt + 2 * t4;
            float2 r0v = { o[nt][0], o[nt][1] };
            float2 r1v = { o[nt][2], o[nt][3] };
            *(float2*)(po + lr0 * HH + c) = r0v;
            *(float2*)(po + lr1 * HH + c) = r1v;
        }
        if (t4 == 0) {
            stats[part_id * 128 + lr0 * 2]     = m0;
            stats[part_id * 128 + lr0 * 2 + 1] = l0;
            stats[part_id * 128 + lr1 * 2]     = m1;
            stats[part_id * 128 + lr1 * 2 + 1] = l1;
        }
    }
}

// ---------------------------------------------------------------------------
// Kernel 3: merge the two KV-split partials for q-tiles 16..31.
// ---------------------------------------------------------------------------
__global__ __launch_bounds__(128) void combine_kernel(
    const float* __restrict__ part, const float* __restrict__ stats,
    float* __restrict__ out)
{
    const int idx = blockIdx.x;          // b*16 + qt16
    const int b = idx >> 4, qt = 16 + (idx & 15);
    const int p0 = idx * 2, p1 = p0 + 1;
    __shared__ float a0s[QT], a1s[QT], invs[QT];
    const int tid = threadIdx.x;
    if (tid < QT) {
        float ma = stats[p0 * 128 + tid * 2], la = stats[p0 * 128 + tid * 2 + 1];
        float mb = stats[p1 * 128 + tid * 2], lb = stats[p1 * 128 + tid * 2 + 1];
        float m = fmaxf(ma, mb);
        float a0 = __expf(ma - m), a1 = __expf(mb - m);
        a0s[tid] = a0; a1s[tid] = a1;
        invs[tid] = 1.f / (a0 * la + a1 * lb);
    }
    __syncthreads();
    const float4* P0 = (const float4*)(part + (size_t)p0 * (QT * HH));
    const float4* P1 = (const float4*)(part + (size_t)p1 * (QT * HH));
    float4* ob = (float4*)(out + ((size_t)b * TT + qt * QT) * HH);
    #pragma unroll 2
    for (int e = tid; e < QT * HH / 4; e += 128) {
        int r = e >> 4;
        float a0 = a0s[r], a1 = a1s[r], iv = invs[r];
        float4 u = P0[e], v = P1[e];
        float4 rres;
        rres.x = (a0 * u.x + a1 * v.x) * iv;
        rres.y = (a0 * u.y + a1 * v.y) * iv;
        rres.z = (a0 * u.z + a1 * v.z) * iv;
        rres.w = (a0 * u.w + a1 * v.w) * iv;
        ob[e] = rres;
    }
}

// ---------------------------------------------------------------------------
// launch
// ---------------------------------------------------------------------------
extern "C" void kernel_launch(void* const* d_in, const int* in_sizes, int n_in,
                              void* d_out, int out_size)
{
    const float* x = (const float*)d_in[0];   // [B, T, C]
    const float* W = (const float*)d_in[1];   // [H, C]
    float* out = (float*)d_out;               // [B, T, H]

    float *kbuf = nullptr, *part = nullptr, *stats = nullptr;
    cudaGetSymbolAddress((void**)&kbuf, g_kbuf);
    cudaGetSymbolAddress((void**)&part, g_part);
    cudaGetSymbolAddress((void**)&stats, g_stats);

    cudaFuncSetAttribute(attn_kernel, cudaFuncAttributeMaxDynamicSharedMemorySize,
                         ATTN_SMEM_BYTES);

    proj_kernel<<<(BB * TT) / PROJ_M, 256>>>(x, W, kbuf);

    dim3 g(48, BB);
    attn_kernel<<<g, 128, ATTN_SMEM_BYTES>>>(kbuf, out, part, stats);

    combine_kernel<<<BB * 16, 128>>>(part, stats, out);
}

// round 5
// speedup vs baseline: 1.9993x; 1.1424x over previous
#include <cuda_runtime.h>
#include <cstdint>

// Problem constants
#define BB 8
#define TT 2048
#define CC 1024
#define HH 64

// k projection scratch, tf32-rounded bits, PAIR-INTERLEAVED columns:
// within each 8-col group, storage order is [0,4,1,5,2,6,3,7] so that the
// mma-pair (c, c+4) is adjacent (one LDS.64).
__device__ float g_kbuf[BB * TT * HH];
// KV-split partials + per-row (m,l)
__device__ float g_part[256 * 64 * 64];
__device__ float g_stats[256 * 64 * 2];

// item order sorted by iteration count (descending), 48 items per batch
__constant__ int c_order[48] = {
    46,47,25,27,28,29,30,31,                 // 8 iters
    44,45,17,19,20,21,22,23,24,26,           // 7
    42,43, 9,11,12,13,14,15,16,18,           // 6
    40,41, 1, 3, 4, 5, 6, 7, 8,10,           // 5
    38,39, 0, 2,                             // 4
    36,37, 34,35, 32,33                      // 3,2,1
};

// ---------------------------------------------------------------------------
// helpers
// ---------------------------------------------------------------------------
__device__ __forceinline__ uint32_t f2t(float x) {
    uint32_t u;
    asm("cvt.rna.tf32.f32 %0, %1;" : "=r"(u) : "f"(x));
    return u;
}

__device__ __forceinline__ void mma8(float* c, const uint32_t* a, const uint32_t* b) {
    asm volatile(
        "mma.sync.aligned.m16n8k8.row.col.f32.tf32.tf32.f32 "
        "{%0,%1,%2,%3}, {%4,%5,%6,%7}, {%8,%9}, {%0,%1,%2,%3};"
        : "+f"(c[0]), "+f"(c[1]), "+f"(c[2]), "+f"(c[3])
        : "r"(a[0]), "r"(a[1]), "r"(a[2]), "r"(a[3]), "r"(b[0]), "r"(b[1]));
}

__device__ __forceinline__ void cpa16(uint32_t dst, const void* src) {
    asm volatile("cp.async.cg.shared.global [%0], [%1], 16;" :: "r"(dst), "l"(src));
}
__device__ __forceinline__ void cpa_commit() {
    asm volatile("cp.async.commit_group;");
}

// ---------------------------------------------------------------------------
// Kernel 1: k = tf32(x @ W^T), interleaved output. 64 rows/block, 256 threads,
// 4-stage cp.async pipeline over 32-col K chunks (32 chunks). 2 CTAs/SM so
// ptxas keeps full register budget (no spills in the pipelined mainloop).
// ---------------------------------------------------------------------------
#define PROJ_M 64
#define PKC 32
#define XS 36
#define WS 36
#define PST 4
#define PROJ_STAGE_F (PROJ_M * XS)           // 2304 floats per x stage (= W stage)
#define PROJ_SMEM_BYTES (PST * 2 * PROJ_STAGE_F * 4)   // 73728

__global__ __launch_bounds__(256, 2) void proj_kernel(
    const float* __restrict__ x, const float* __restrict__ W, float* __restrict__ ko)
{
    extern __shared__ float psm[];
    float* sX = psm;                          // PST stages of 64x36
    float* sW = psm + PST * PROJ_STAGE_F;     // PST stages of 64x36
    const uint32_t sXa = (uint32_t)__cvta_generic_to_shared(sX);
    const uint32_t sWa = (uint32_t)__cvta_generic_to_shared(sW);

    const int tid = threadIdx.x;
    const int row0 = blockIdx.x * PROJ_M;
    const int w = tid >> 5, lane = tid & 31, gid = lane >> 2, t4 = lane & 3;
    const int mw = w & 3;
    const int nh = w >> 2;

    // loader task split: tasks t in {tid, tid+256}; r = t>>3, c4 = t&7
    const int r0 = tid >> 3, c40 = tid & 7;
    const int r1 = (tid + 256) >> 3, c41 = (tid + 256) & 7;

    auto issue_chunk = [&](int ci) {
        int st = ci & (PST - 1);
        uint32_t dx = sXa + (uint32_t)(st * PROJ_STAGE_F) * 4;
        uint32_t dw = sWa + (uint32_t)(st * PROJ_STAGE_F) * 4;
        const float* xsrc = x + (size_t)row0 * CC + ci * PKC;
        const float* wsrc = W + ci * PKC;
        cpa16(dx + (uint32_t)(r0 * XS + c40 * 4) * 4, xsrc + (size_t)r0 * CC + c40 * 4);
        cpa16(dx + (uint32_t)(r1 * XS + c41 * 4) * 4, xsrc + (size_t)r1 * CC + c41 * 4);
        cpa16(dw + (uint32_t)(r0 * WS + c40 * 4) * 4, wsrc + (size_t)r0 * CC + c40 * 4);
        cpa16(dw + (uint32_t)(r1 * WS + c41 * 4) * 4, wsrc + (size_t)r1 * CC + c41 * 4);
    };

    float acc[4][4];
    #pragma unroll
    for (int i = 0; i < 4; i++)
        #pragma unroll
        for (int l = 0; l < 4; l++) acc[i][l] = 0.f;

    // prologue: 3 chunks in flight
    issue_chunk(0); cpa_commit();
    issue_chunk(1); cpa_commit();
    issue_chunk(2); cpa_commit();

    const int NCHUNK = CC / PKC;  // 32
    for (int ci = 0; ci < NCHUNK; ci++) {
        asm volatile("cp.async.wait_group 2;");
        __syncthreads();
        if (ci + 3 < NCHUNK) issue_chunk(ci + 3);
        cpa_commit();   // empty groups keep the pending-count uniform

        const float* bx = sX + (ci & (PST - 1)) * PROJ_STAGE_F;
        const float* bw = sW + (ci & (PST - 1)) * PROJ_STAGE_F;
        #pragma unroll
        for (int k0 = 0; k0 < PKC; k0 += 8) {
            uint32_t a[4];
            const float* pq = bx + (16 * mw + gid) * XS + k0 + t4;
            a[0] = f2t(pq[0]);
            a[1] = f2t(pq[8 * XS]);
            a[2] = f2t(pq[4]);
            a[3] = f2t(pq[8 * XS + 4]);
            #pragma unroll
            for (int nt = 0; nt < 4; nt++) {
                const float* pw = bw + (32 * nh + 8 * nt + gid) * WS + k0 + t4;
                uint32_t bb[2] = { f2t(pw[0]), f2t(pw[4]) };
                mma8(acc[nt], a, bb);
            }
        }
    }

    // epilogue: tf32-rounded bits, pair-interleaved column positions
    const int pe = 2 * ((2 * t4) & 3) + ((2 * t4) >> 2);
    const int po = 2 * ((2 * t4 + 1) & 3) + ((2 * t4 + 1) >> 2);
    #pragma unroll
    for (int nt = 0; nt < 4; nt++) {
        int r = row0 + 16 * mw + gid;
        int cb = 32 * nh + 8 * nt;
        ko[(size_t)r * HH + cb + pe]       = __uint_as_float(f2t(acc[nt][0]));
        ko[(size_t)r * HH + cb + po]       = __uint_as_float(f2t(acc[nt][1]));
        ko[(size_t)(r + 8) * HH + cb + pe] = __uint_as_float(f2t(acc[nt][2]));
        ko[(size_t)(r + 8) * HH + cb + po] = __uint_as_float(f2t(acc[nt][3]));
    }
}

// ---------------------------------------------------------------------------
// Kernel 2: causal flash attention, KV-split, interleaved k-buffer.
// 128 threads, 3 CTAs/SM. QK frags via LDS.64 (pair-interleaved layout).
// ---------------------------------------------------------------------------
#define QT 64
#define KT 128
#define QS 72
#define KS 72
#define SCALE 0.03125f

#define ATTN_SMEM_FLOATS (QT * QS + KT * KS)
#define ATTN_SMEM_BYTES  (ATTN_SMEM_FLOATS * 4)

__global__ __launch_bounds__(128, 3) void attn_kernel(
    const float* __restrict__ kb, float* __restrict__ out,
    float* __restrict__ part, float* __restrict__ stats)
{
    extern __shared__ float sm[];
    float* sQ = sm;             // QT*QS
    float* sK = sQ + QT * QS;   // KT*KS

    const int tid = threadIdx.x;
    const int bid = blockIdx.x;
    // boustrophedon rank so each SM's resident blocks have balanced work
    const int rank = (bid < 148) ? bid : ((bid < 296) ? (443 - bid) : bid);
    const int item = c_order[rank >> 3];
    const int b = rank & 7;

    int qt, j0, j1, split;
    bool is_split;
    if (item < 32) {
        qt = 16 + (item >> 1);
        split = item & 1;
        int jm = qt >> 1;
        int h = (jm + 1) >> 1;
        if (split == 0) { j0 = 0; j1 = h - 1; }
        else            { j0 = h; j1 = jm; }
        is_split = true;
    } else {
        qt = item - 32;
        split = 0;
        j0 = 0; j1 = qt >> 1;
        is_split = false;
    }
    const int jmaskg = qt >> 1;
    const int qrow0 = qt * QT;
    const float* kbase = kb + (size_t)b * TT * HH;

    const int w = tid >> 5, lane = tid & 31, gid = lane >> 2, t4 = lane & 3;
    const int srcA = (lane & ~3) | (t4 >> 1);
    const int srcB = srcA + 2;
    const bool odd = (t4 & 1);
    // PV column permutation: natural h col (8nt+gid) lives at 8nt + pvoff
    const int pvoff = 2 * (gid & 3) + (gid >> 2);

    // load Q tile (scaled; power-of-two scale keeps tf32 bits; interleave is
    // a pure permutation so a plain copy preserves it)
    #pragma unroll
    for (int i = tid; i < QT * (HH / 4); i += 128) {
        int r = i >> 4, c4 = i & 15;
        float4 v = *(const float4*)(kbase + (size_t)(qrow0 + r) * HH + c4 * 4);
        v.x *= SCALE; v.y *= SCALE; v.z *= SCALE; v.w *= SCALE;
        *(float4*)&sQ[r * QS + c4 * 4] = v;
    }

    float m0 = -1e30f, m1 = -1e30f, l0 = 0.f, l1 = 0.f;
    const int rg0 = qrow0 + 16 * w + gid;
    const int rg1 = rg0 + 8;

    float o[8][4];
    #pragma unroll
    for (int i = 0; i < 8; i++)
        #pragma unroll
        for (int l = 0; l < 4; l++) o[i][l] = 0.f;

    for (int j = j0; j <= j1; j++) {
        __syncthreads();
        #pragma unroll
        for (int i = tid; i < KT * (HH / 4); i += 128) {
            int r = i >> 4, c4 = i & 15;
            *(float4*)&sK[r * KS + c4 * 4] =
                *(const float4*)(kbase + (size_t)(j * KT + r) * HH + c4 * 4);
        }
        __syncthreads();

        // ---- S = Q K^T : frags via LDS.64 from interleaved layout ----
        float s[16][4];
        #pragma unroll
        for (int nt = 0; nt < 16; nt++)
            #pragma unroll
            for (int l = 0; l < 4; l++) s[nt][l] = 0.f;

        #pragma unroll
        for (int k0 = 0; k0 < HH; k0 += 8) {
            uint32_t a[4];
            float2 qa = *(const float2*)&sQ[(16 * w + gid) * QS + k0 + 2 * t4];
            float2 qb = *(const float2*)&sQ[(16 * w + gid + 8) * QS + k0 + 2 * t4];
            a[0] = __float_as_uint(qa.x);
            a[1] = __float_as_uint(qb.x);
            a[2] = __float_as_uint(qa.y);
            a[3] = __float_as_uint(qb.y);
            #pragma unroll
            for (int nt = 0; nt < 16; nt++) {
                float2 kv = *(const float2*)&sK[(8 * nt + gid) * KS + k0 + 2 * t4];
                uint32_t bb[2] = { __float_as_uint(kv.x), __float_as_uint(kv.y) };
                mma8(s[nt], a, bb);
            }
        }

        // ---- causal mask (diagonal tile only) ----
        if (j == jmaskg) {
            #pragma unroll
            for (int nt = 0; nt < 16; nt++) {
                int kc = j * KT + 8 * nt + 2 * t4;
                if (kc     > rg0) s[nt][0] = -1e30f;
                if (kc + 1 > rg0) s[nt][1] = -1e30f;
                if (kc     > rg1) s[nt][2] = -1e30f;
                if (kc + 1 > rg1) s[nt][3] = -1e30f;
            }
        }

        // ---- online softmax ----
        float mx0 = -1e30f, mx1 = -1e30f;
        #pragma unroll
        for (int nt = 0; nt < 16; nt++) {
            mx0 = fmaxf(mx0, fmaxf(s[nt][0], s[nt][1]));
            mx1 = fmaxf(mx1, fmaxf(s[nt][2], s[nt][3]));
        }
        mx0 = fmaxf(mx0, __shfl_xor_sync(0xffffffffu, mx0, 1));
        mx0 = fmaxf(mx0, __shfl_xor_sync(0xffffffffu, mx0, 2));
        mx1 = fmaxf(mx1, __shfl_xor_sync(0xffffffffu, mx1, 1));
        mx1 = fmaxf(mx1, __shfl_xor_sync(0xffffffffu, mx1, 2));

        float mn0 = fmaxf(m0, mx0), mn1 = fmaxf(m1, mx1);
        float al0 = __expf(m0 - mn0), al1 = __expf(m1 - mn1);
        m0 = mn0; m1 = mn1;

        float sum0 = 0.f, sum1 = 0.f;
        #pragma unroll
        for (int nt = 0; nt < 16; nt++) {
            s[nt][0] = __expf(s[nt][0] - mn0);
            s[nt][1] = __expf(s[nt][1] - mn0);
            s[nt][2] = __expf(s[nt][2] - mn1);
            s[nt][3] = __expf(s[nt][3] - mn1);
            sum0 += s[nt][0] + s[nt][1];
            sum1 += s[nt][2] + s[nt][3];
        }
        sum0 += __shfl_xor_sync(0xffffffffu, sum0, 1);
        sum0 += __shfl_xor_sync(0xffffffffu, sum0, 2);
        sum1 += __shfl_xor_sync(0xffffffffu, sum1, 1);
        sum1 += __shfl_xor_sync(0xffffffffu, sum1, 2);
        l0 = l0 * al0 + sum0;
        l1 = l1 * al1 + sum1;

        #pragma unroll
        for (int nt = 0; nt < 8; nt++) {
            o[nt][0] *= al0; o[nt][1] *= al0; o[nt][2] *= al1; o[nt][3] *= al1;
        }

        // ---- O += P V ----
        #pragma unroll
        for (int kk = 0; kk < 16; kk++) {
            float v00 = __shfl_sync(0xffffffffu, s[kk][0], srcA);
            float v01 = __shfl_sync(0xffffffffu, s[kk][1], srcA);
            float v10 = __shfl_sync(0xffffffffu, s[kk][0], srcB);
            float v11 = __shfl_sync(0xffffffffu, s[kk][1], srcB);
            float v20 = __shfl_sync(0xffffffffu, s[kk][2], srcA);
            float v21 = __shfl_sync(0xffffffffu, s[kk][3], srcA);
            float v30 = __shfl_sync(0xffffffffu, s[kk][2], srcB);
            float v31 = __shfl_sync(0xffffffffu, s[kk][3], srcB);
            uint32_t a[4];
            a[0] = f2t(odd ? v01 : v00);
            a[1] = f2t(odd ? v21 : v20);
            a[2] = f2t(odd ? v11 : v10);
            a[3] = f2t(odd ? v31 : v30);
            const float* rowp = sK + (8 * kk + t4) * KS + pvoff;
            #pragma unroll
            for (int nt = 0; nt < 8; nt++) {
                uint32_t bb[2] = { __float_as_uint(rowp[8 * nt]),
                                   __float_as_uint(rowp[8 * nt + 4 * KS]) };
                mma8(o[nt], a, bb);
            }
        }
    }

    if (!is_split) {
        float il0 = 1.f / l0, il1 = 1.f / l1;
        float* ob = out + (size_t)b * TT * HH;
        #pragma unroll
        for (int nt = 0; nt < 8; nt++) {
            int c = 8 * nt + 2 * t4;
            float2 r0v = { o[nt][0] * il0, o[nt][1] * il0 };
            float2 r1v = { o[nt][2] * il1, o[nt][3] * il1 };
            *(float2*)(ob + (size_t)rg0 * HH + c) = r0v;
            *(float2*)(ob + (size_t)rg1 * HH + c) = r1v;
        }
    } else {
        const int part_id = (b * 16 + (qt - 16)) * 2 + split;
        float* po = part + (size_t)part_id * (QT * HH);
        const int lr0 = 16 * w + gid, lr1 = lr0 + 8;
        #pragma unroll
        for (int nt = 0; nt < 8; nt++) {
            int c = 8 * nt + 2 * t4;
            float2 r0v = { o[nt][0], o[nt][1] };
            float2 r1v = { o[nt][2], o[nt][3] };
            *(float2*)(po + lr0 * HH + c) = r0v;
            *(float2*)(po + lr1 * HH + c) = r1v;
        }
        if (t4 == 0) {
            stats[part_id * 128 + lr0 * 2]     = m0;
            stats[part_id * 128 + lr0 * 2 + 1] = l0;
            stats[part_id * 128 + lr1 * 2]     = m1;
            stats[part_id * 128 + lr1 * 2 + 1] = l1;
        }
    }
}

// ---------------------------------------------------------------------------
// Kernel 3: merge KV-split partials for q-tiles 16..31.
// ---------------------------------------------------------------------------
__global__ __launch_bounds__(128) void combine_kernel(
    const float* __restrict__ part, const float* __restrict__ stats,
    float* __restrict__ out)
{
    const int idx = blockIdx.x;
    const int b = idx >> 4, qt = 16 + (idx & 15);
    const int p0 = idx * 2, p1 = p0 + 1;
    __shared__ float a0s[QT], a1s[QT], invs[QT];
    const int tid = threadIdx.x;
    if (tid < QT) {
        float ma = stats[p0 * 128 + tid * 2], la = stats[p0 * 128 + tid * 2 + 1];
        float mb = stats[p1 * 128 + tid * 2], lb = stats[p1 * 128 + tid * 2 + 1];
        float m = fmaxf(ma, mb);
        float a0 = __expf(ma - m), a1 = __expf(mb - m);
        a0s[tid] = a0; a1s[tid] = a1;
        invs[tid] = 1.f / (a0 * la + a1 * lb);
    }
    __syncthreads();
    const float4* P0 = (const float4*)(part + (size_t)p0 * (QT * HH));
    const float4* P1 = (const float4*)(part + (size_t)p1 * (QT * HH));
    float4* ob = (float4*)(out + ((size_t)b * TT + qt * QT) * HH);
    #pragma unroll 2
    for (int e = tid; e < QT * HH / 4; e += 128) {
        int r = e >> 4;
        float a0 = a0s[r], a1 = a1s[r], iv = invs[r];
        float4 u = P0[e], v = P1[e];
        float4 rres;
        rres.x = (a0 * u.x + a1 * v.x) * iv;
        rres.y = (a0 * u.y + a1 * v.y) * iv;
        rres.z = (a0 * u.z + a1 * v.z) * iv;
        rres.w = (a0 * u.w + a1 * v.w) * iv;
        ob[e] = rres;
    }
}

// ---------------------------------------------------------------------------
// launch
// ---------------------------------------------------------------------------
extern "C" void kernel_launch(void* const* d_in, const int* in_sizes, int n_in,
                              void* d_out, int out_size)
{
    const float* x = (const float*)d_in[0];   // [B, T, C]
    const float* W = (const float*)d_in[1];   // [H, C]
    float* out = (float*)d_out;               // [B, T, H]

    float *kbuf = nullptr, *part = nullptr, *stats = nullptr;
    cudaGetSymbolAddress((void**)&kbuf, g_kbuf);
    cudaGetSymbolAddress((void**)&part, g_part);
    cudaGetSymbolAddress((void**)&stats, g_stats);

    cudaFuncSetAttribute(proj_kernel, cudaFuncAttributeMaxDynamicSharedMemorySize,
                         PROJ_SMEM_BYTES);
    cudaFuncSetAttribute(attn_kernel, cudaFuncAttributeMaxDynamicSharedMemorySize,
                         ATTN_SMEM_BYTES);

    proj_kernel<<<(BB * TT) / PROJ_M, 256, PROJ_SMEM_BYTES>>>(x, W, kbuf);

    attn_kernel<<<48 * BB, 128, ATTN_SMEM_BYTES>>>(kbuf, out, part, stats);

    combine_kernel<<<BB * 16, 128>>>(part, stats, out);
}

// round 6
// speedup vs baseline: 2.1492x; 1.0750x over previous
#include <cuda_runtime.h>
#include <cstdint>

// Problem constants
#define BB 8
#define TT 2048
#define CC 1024
#define HH 64

// k projection scratch, tf32-rounded bits, PAIR-INTERLEAVED columns:
// within each 8-col group, storage order is [0,4,1,5,2,6,3,7] so that the
// mma-pair (c, c+4) is adjacent (one LDS.64).
__device__ float g_kbuf[BB * TT * HH];
// W pre-converted to tf32 bits, same pair-interleave within 8-col k-groups
__device__ float g_wt[HH * CC];
// KV-split partials + per-row (m,l)
__device__ float g_part[256 * 64 * 64];
__device__ float g_stats[256 * 64 * 2];

// item order sorted by iteration count (descending), 48 items per batch
__constant__ int c_order[48] = {
    46,47,25,27,28,29,30,31,                 // 8 iters
    44,45,17,19,20,21,22,23,24,26,           // 7
    42,43, 9,11,12,13,14,15,16,18,           // 6
    40,41, 1, 3, 4, 5, 6, 7, 8,10,           // 5
    38,39, 0, 2,                             // 4
    36,37, 34,35, 32,33                      // 3,2,1
};

// ---------------------------------------------------------------------------
// helpers
// ---------------------------------------------------------------------------
__device__ __forceinline__ uint32_t f2t(float x) {
    uint32_t u;
    asm("cvt.rna.tf32.f32 %0, %1;" : "=r"(u) : "f"(x));
    return u;
}

__device__ __forceinline__ void mma8(float* c, const uint32_t* a, const uint32_t* b) {
    asm volatile(
        "mma.sync.aligned.m16n8k8.row.col.f32.tf32.tf32.f32 "
        "{%0,%1,%2,%3}, {%4,%5,%6,%7}, {%8,%9}, {%0,%1,%2,%3};"
        : "+f"(c[0]), "+f"(c[1]), "+f"(c[2]), "+f"(c[3])
        : "r"(a[0]), "r"(a[1]), "r"(a[2]), "r"(a[3]), "r"(b[0]), "r"(b[1]));
}

__device__ __forceinline__ void cpa16(uint32_t dst, const void* src) {
    asm volatile("cp.async.cg.shared.global [%0], [%1], 16;" :: "r"(dst), "l"(src));
}
__device__ __forceinline__ void cpa_commit() {
    asm volatile("cp.async.commit_group;");
}

// ---------------------------------------------------------------------------
// Kernel 0: W [64,1024] fp32 -> tf32 bits, pair-interleaved in 8-col groups.
// ---------------------------------------------------------------------------
__global__ __launch_bounds__(256) void wconv_kernel(
    const float* __restrict__ W, float* __restrict__ wt)
{
    const int row = blockIdx.x;            // 64 rows
    const int t = threadIdx.x;             // 256 threads, 4 cols each
    float4 v = *(const float4*)(W + (size_t)row * CC + t * 4);
    // cols 4t..4t+3; group g = t>>1; within-8 offset base = (t&1)*4
    int g = t >> 1;
    int w8b = (t & 1) * 4;                 // 0 or 4
    float* dst = wt + (size_t)row * CC + g * 8;
    // pos(w8) = 2*(w8&3) + (w8>>2)
    dst[2 * ((w8b + 0) & 3) + ((w8b + 0) >> 2)] = __uint_as_float(f2t(v.x));
    dst[2 * ((w8b + 1) & 3) + ((w8b + 1) >> 2)] = __uint_as_float(f2t(v.y));
    dst[2 * ((w8b + 2) & 3) + ((w8b + 2) >> 2)] = __uint_as_float(f2t(v.z));
    dst[2 * ((w8b + 3) & 3) + ((w8b + 3) >> 2)] = __uint_as_float(f2t(v.w));
}

// ---------------------------------------------------------------------------
// Kernel 1: k = tf32(x @ W^T), interleaved output. 128 rows/block (grid 128),
// 256 threads = 8 warps (4 m-groups of 32 rows x 2 n-groups of 32 cols),
// 2 m-tiles per warp so W-frag loads amortize; W frags are LDS.64, no cvt.
// 4-stage cp.async pipeline over 32-col K chunks.
// ---------------------------------------------------------------------------
#define PROJ_M 128
#define PKC 32
#define XS 36
#define WTS 40
#define PST 4
#define PROJ_XSF (PROJ_M * XS)               // 4608 floats per x stage
#define PROJ_WSF (HH * WTS)                  // 2560 floats per W stage
#define PROJ_STF (PROJ_XSF + PROJ_WSF)       // 7168
#define PROJ_SMEM_BYTES (PST * PROJ_STF * 4) // 114688

__global__ __launch_bounds__(256, 1) void proj_kernel(
    const float* __restrict__ x, const float* __restrict__ wt, float* __restrict__ ko)
{
    extern __shared__ float psm[];
    const uint32_t sba = (uint32_t)__cvta_generic_to_shared(psm);

    const int tid = threadIdx.x;
    const int row0 = blockIdx.x * PROJ_M;
    const int w = tid >> 5, lane = tid & 31, gid = lane >> 2, t4 = lane & 3;
    const int mw = w & 3;      // m-group: 32 rows at 32*mw
    const int nh = w >> 2;     // n-group: 32 cols at 32*nh

    // x loader: 1024 float4 tasks -> 4 per thread; W loader: 512 -> 2 per thread
    const int xr[4] = { tid >> 3, (tid + 256) >> 3, (tid + 512) >> 3, (tid + 768) >> 3 };
    const int xc = tid & 7;
    const int wr0 = tid >> 3, wr1 = (tid + 256) >> 3;
    const int wc = tid & 7;

    auto issue_chunk = [&](int ci) {
        int st = ci & (PST - 1);
        uint32_t dx = sba + (uint32_t)(st * PROJ_STF) * 4;
        uint32_t dw = dx + (uint32_t)PROJ_XSF * 4;
        const float* xsrc = x + (size_t)row0 * CC + ci * PKC;
        const float* wsrc = wt + ci * PKC;
        #pragma unroll
        for (int t = 0; t < 4; t++)
            cpa16(dx + (uint32_t)(xr[t] * XS + xc * 4) * 4,
                  xsrc + (size_t)xr[t] * CC + xc * 4);
        cpa16(dw + (uint32_t)(wr0 * WTS + wc * 4) * 4, wsrc + (size_t)wr0 * CC + wc * 4);
        cpa16(dw + (uint32_t)(wr1 * WTS + wc * 4) * 4, wsrc + (size_t)wr1 * CC + wc * 4);
    };

    float acc[2][4][4];
    #pragma unroll
    for (int m = 0; m < 2; m++)
        #pragma unroll
        for (int i = 0; i < 4; i++)
            #pragma unroll
            for (int l = 0; l < 4; l++) acc[m][i][l] = 0.f;

    issue_chunk(0); cpa_commit();
    issue_chunk(1); cpa_commit();
    issue_chunk(2); cpa_commit();

    const int NCHUNK = CC / PKC;  // 32
    for (int ci = 0; ci < NCHUNK; ci++) {
        asm volatile("cp.async.wait_group 2;");
        __syncthreads();
        if (ci + 3 < NCHUNK) issue_chunk(ci + 3);
        cpa_commit();

        const float* bx = psm + (ci & (PST - 1)) * PROJ_STF;
        const float* bw = bx + PROJ_XSF;
        #pragma unroll
        for (int k0 = 0; k0 < PKC; k0 += 8) {
            uint32_t a[2][4];
            #pragma unroll
            for (int mt = 0; mt < 2; mt++) {
                const float* pq = bx + (32 * mw + 16 * mt + gid) * XS + k0 + t4;
                a[mt][0] = f2t(pq[0]);
                a[mt][1] = f2t(pq[8 * XS]);
                a[mt][2] = f2t(pq[4]);
                a[mt][3] = f2t(pq[8 * XS + 4]);
            }
            #pragma unroll
            for (int nt = 0; nt < 4; nt++) {
                float2 kv = *(const float2*)&bw[(32 * nh + 8 * nt + gid) * WTS + k0 + 2 * t4];
                uint32_t bb[2] = { __float_as_uint(kv.x), __float_as_uint(kv.y) };
                mma8(acc[0][nt], a[0], bb);
                mma8(acc[1][nt], a[1], bb);
            }
        }
    }

    // epilogue: tf32-rounded bits, pair-interleaved column positions
    const int pe = 2 * ((2 * t4) & 3) + ((2 * t4) >> 2);
    const int po = 2 * ((2 * t4 + 1) & 3) + ((2 * t4 + 1) >> 2);
    #pragma unroll
    for (int mt = 0; mt < 2; mt++)
        #pragma unroll
        for (int nt = 0; nt < 4; nt++) {
            int r = row0 + 32 * mw + 16 * mt + gid;
            int cb = 32 * nh + 8 * nt;
            ko[(size_t)r * HH + cb + pe]       = __uint_as_float(f2t(acc[mt][nt][0]));
            ko[(size_t)r * HH + cb + po]       = __uint_as_float(f2t(acc[mt][nt][1]));
            ko[(size_t)(r + 8) * HH + cb + pe] = __uint_as_float(f2t(acc[mt][nt][2]));
            ko[(size_t)(r + 8) * HH + cb + po] = __uint_as_float(f2t(acc[mt][nt][3]));
        }
}

// ---------------------------------------------------------------------------
// Kernel 2: causal flash attention, KV-split, interleaved k-buffer.
// 128 threads, 3 CTAs/SM. QK frags via LDS.64 (pair-interleaved layout).
// ---------------------------------------------------------------------------
#define QT 64
#define KT 128
#define QS 72
#define KS 72
#define SCALE 0.03125f

#define ATTN_SMEM_FLOATS (QT * QS + KT * KS)
#define ATTN_SMEM_BYTES  (ATTN_SMEM_FLOATS * 4)

__global__ __launch_bounds__(128, 3) void attn_kernel(
    const float* __restrict__ kb, float* __restrict__ out,
    float* __restrict__ part, float* __restrict__ stats)
{
    extern __shared__ float sm[];
    float* sQ = sm;             // QT*QS
    float* sK = sQ + QT * QS;   // KT*KS

    const int tid = threadIdx.x;
    const int bid = blockIdx.x;
    // boustrophedon rank so each SM's resident blocks have balanced work
    const int rank = (bid < 148) ? bid : ((bid < 296) ? (443 - bid) : bid);
    const int item = c_order[rank >> 3];
    const int b = rank & 7;

    int qt, j0, j1, split;
    bool is_split;
    if (item < 32) {
        qt = 16 + (item >> 1);
        split = item & 1;
        int jm = qt >> 1;
        int h = (jm + 1) >> 1;
        if (split == 0) { j0 = 0; j1 = h - 1; }
        else            { j0 = h; j1 = jm; }
        is_split = true;
    } else {
        qt = item - 32;
        split = 0;
        j0 = 0; j1 = qt >> 1;
        is_split = false;
    }
    const int jmaskg = qt >> 1;
    const int qrow0 = qt * QT;
    const float* kbase = kb + (size_t)b * TT * HH;

    const int w = tid >> 5, lane = tid & 31, gid = lane >> 2, t4 = lane & 3;
    const int srcA = (lane & ~3) | (t4 >> 1);
    const int srcB = srcA + 2;
    const bool odd = (t4 & 1);
    // PV column permutation: natural h col (8nt+gid) lives at 8nt + pvoff
    const int pvoff = 2 * (gid & 3) + (gid >> 2);

    // load Q tile (scaled; power-of-two scale keeps tf32 bits; interleave is
    // a pure permutation so a plain copy preserves it)
    #pragma unroll
    for (int i = tid; i < QT * (HH / 4); i += 128) {
        int r = i >> 4, c4 = i & 15;
        float4 v = *(const float4*)(kbase + (size_t)(qrow0 + r) * HH + c4 * 4);
        v.x *= SCALE; v.y *= SCALE; v.z *= SCALE; v.w *= SCALE;
        *(float4*)&sQ[r * QS + c4 * 4] = v;
    }

    float m0 = -1e30f, m1 = -1e30f, l0 = 0.f, l1 = 0.f;
    const int rg0 = qrow0 + 16 * w + gid;
    const int rg1 = rg0 + 8;

    float o[8][4];
    #pragma unroll
    for (int i = 0; i < 8; i++)
        #pragma unroll
        for (int l = 0; l < 4; l++) o[i][l] = 0.f;

    for (int j = j0; j <= j1; j++) {
        __syncthreads();
        #pragma unroll
        for (int i = tid; i < KT * (HH / 4); i += 128) {
            int r = i >> 4, c4 = i & 15;
            *(float4*)&sK[r * KS + c4 * 4] =
                *(const float4*)(kbase + (size_t)(j * KT + r) * HH + c4 * 4);
        }
        __syncthreads();

        // ---- S = Q K^T : frags via LDS.64 from interleaved layout ----
        float s[16][4];
        #pragma unroll
        for (int nt = 0; nt < 16; nt++)
            #pragma unroll
            for (int l = 0; l < 4; l++) s[nt][l] = 0.f;

        #pragma unroll
        for (int k0 = 0; k0 < HH; k0 += 8) {
            uint32_t a[4];
            float2 qa = *(const float2*)&sQ[(16 * w + gid) * QS + k0 + 2 * t4];
            float2 qb = *(const float2*)&sQ[(16 * w + gid + 8) * QS + k0 + 2 * t4];
            a[0] = __float_as_uint(qa.x);
            a[1] = __float_as_uint(qb.x);
            a[2] = __float_as_uint(qa.y);
            a[3] = __float_as_uint(qb.y);
            #pragma unroll
            for (int nt = 0; nt < 16; nt++) {
                float2 kv = *(const float2*)&sK[(8 * nt + gid) * KS + k0 + 2 * t4];
                uint32_t bb[2] = { __float_as_uint(kv.x), __float_as_uint(kv.y) };
                mma8(s[nt], a, bb);
            }
        }

        // ---- causal mask (diagonal tile only) ----
        if (j == jmaskg) {
            #pragma unroll
            for (int nt = 0; nt < 16; nt++) {
                int kc = j * KT + 8 * nt + 2 * t4;
                if (kc     > rg0) s[nt][0] = -1e30f;
                if (kc + 1 > rg0) s[nt][1] = -1e30f;
                if (kc     > rg1) s[nt][2] = -1e30f;
                if (kc + 1 > rg1) s[nt][3] = -1e30f;
            }
        }

        // ---- online softmax ----
        float mx0 = -1e30f, mx1 = -1e30f;
        #pragma unroll
        for (int nt = 0; nt < 16; nt++) {
            mx0 = fmaxf(mx0, fmaxf(s[nt][0], s[nt][1]));
            mx1 = fmaxf(mx1, fmaxf(s[nt][2], s[nt][3]));
        }
        mx0 = fmaxf(mx0, __shfl_xor_sync(0xffffffffu, mx0, 1));
        mx0 = fmaxf(mx0, __shfl_xor_sync(0xffffffffu, mx0, 2));
        mx1 = fmaxf(mx1, __shfl_xor_sync(0xffffffffu, mx1, 1));
        mx1 = fmaxf(mx1, __shfl_xor_sync(0xffffffffu, mx1, 2));

        float mn0 = fmaxf(m0, mx0), mn1 = fmaxf(m1, mx1);
        float al0 = __expf(m0 - mn0), al1 = __expf(m1 - mn1);
        m0 = mn0; m1 = mn1;

        float sum0 = 0.f, sum1 = 0.f;
        #pragma unroll
        for (int nt = 0; nt < 16; nt++) {
            s[nt][0] = __expf(s[nt][0] - mn0);
            s[nt][1] = __expf(s[nt][1] - mn0);
            s[nt][2] = __expf(s[nt][2] - mn1);
            s[nt][3] = __expf(s[nt][3] - mn1);
            sum0 += s[nt][0] + s[nt][1];
            sum1 += s[nt][2] + s[nt][3];
        }
        sum0 += __shfl_xor_sync(0xffffffffu, sum0, 1);
        sum0 += __shfl_xor_sync(0xffffffffu, sum0, 2);
        sum1 += __shfl_xor_sync(0xffffffffu, sum1, 1);
        sum1 += __shfl_xor_sync(0xffffffffu, sum1, 2);
        l0 = l0 * al0 + sum0;
        l1 = l1 * al1 + sum1;

        #pragma unroll
        for (int nt = 0; nt < 8; nt++) {
            o[nt][0] *= al0; o[nt][1] *= al0; o[nt][2] *= al1; o[nt][3] *= al1;
        }

        // ---- O += P V ----
        #pragma unroll
        for (int kk = 0; kk < 16; kk++) {
            float v00 = __shfl_sync(0xffffffffu, s[kk][0], srcA);
            float v01 = __shfl_sync(0xffffffffu, s[kk][1], srcA);
            float v10 = __shfl_sync(0xffffffffu, s[kk][0], srcB);
            float v11 = __shfl_sync(0xffffffffu, s[kk][1], srcB);
            float v20 = __shfl_sync(0xffffffffu, s[kk][2], srcA);
            float v21 = __shfl_sync(0xffffffffu, s[kk][3], srcA);
            float v30 = __shfl_sync(0xffffffffu, s[kk][2], srcB);
            float v31 = __shfl_sync(0xffffffffu, s[kk][3], srcB);
            uint32_t a[4];
            a[0] = f2t(odd ? v01 : v00);
            a[1] = f2t(odd ? v21 : v20);
            a[2] = f2t(odd ? v11 : v10);
            a[3] = f2t(odd ? v31 : v30);
            const float* rowp = sK + (8 * kk + t4) * KS + pvoff;
            #pragma unroll
            for (int nt = 0; nt < 8; nt++) {
                uint32_t bb[2] = { __float_as_uint(rowp[8 * nt]),
                                   __float_as_uint(rowp[8 * nt + 4 * KS]) };
                mma8(o[nt], a, bb);
            }
        }
    }

    if (!is_split) {
        float il0 = 1.f / l0, il1 = 1.f / l1;
        float* ob = out + (size_t)b * TT * HH;
        #pragma unroll
        for (int nt = 0; nt < 8; nt++) {
            int c = 8 * nt + 2 * t4;
            float2 r0v = { o[nt][0] * il0, o[nt][1] * il0 };
            float2 r1v = { o[nt][2] * il1, o[nt][3] * il1 };
            *(float2*)(ob + (size_t)rg0 * HH + c) = r0v;
            *(float2*)(ob + (size_t)rg1 * HH + c) = r1v;
        }
    } else {
        const int part_id = (b * 16 + (qt - 16)) * 2 + split;
        float* po = part + (size_t)part_id * (QT * HH);
        const int lr0 = 16 * w + gid, lr1 = lr0 + 8;
        #pragma unroll
        for (int nt = 0; nt < 8; nt++) {
            int c = 8 * nt + 2 * t4;
            float2 r0v = { o[nt][0], o[nt][1] };
            float2 r1v = { o[nt][2], o[nt][3] };
            *(float2*)(po + lr0 * HH + c) = r0v;
            *(float2*)(po + lr1 * HH + c) = r1v;
        }
        if (t4 == 0) {
            stats[part_id * 128 + lr0 * 2]     = m0;
            stats[part_id * 128 + lr0 * 2 + 1] = l0;
            stats[part_id * 128 + lr1 * 2]     = m1;
            stats[part_id * 128 + lr1 * 2 + 1] = l1;
        }
    }
}

// ---------------------------------------------------------------------------
// Kernel 3: merge KV-split partials for q-tiles 16..31.
// ---------------------------------------------------------------------------
__global__ __launch_bounds__(128) void combine_kernel(
    const float* __restrict__ part, const float* __restrict__ stats,
    float* __restrict__ out)
{
    const int idx = blockIdx.x;
    const int b = idx >> 4, qt = 16 + (idx & 15);
    const int p0 = idx * 2, p1 = p0 + 1;
    __shared__ float a0s[QT], a1s[QT], invs[QT];
    const int tid = threadIdx.x;
    if (tid < QT) {
        float ma = stats[p0 * 128 + tid * 2], la = stats[p0 * 128 + tid * 2 + 1];
        float mb = stats[p1 * 128 + tid * 2], lb = stats[p1 * 128 + tid * 2 + 1];
        float m = fmaxf(ma, mb);
        float a0 = __expf(ma - m), a1 = __expf(mb - m);
        a0s[tid] = a0; a1s[tid] = a1;
        invs[tid] = 1.f / (a0 * la + a1 * lb);
    }
    __syncthreads();
    const float4* P0 = (const float4*)(part + (size_t)p0 * (QT * HH));
    const float4* P1 = (const float4*)(part + (size_t)p1 * (QT * HH));
    float4* ob = (float4*)(out + ((size_t)b * TT + qt * QT) * HH);
    #pragma unroll 2
    for (int e = tid; e < QT * HH / 4; e += 128) {
        int r = e >> 4;
        float a0 = a0s[r], a1 = a1s[r], iv = invs[r];
        float4 u = P0[e], v = P1[e];
        float4 rres;
        rres.x = (a0 * u.x + a1 * v.x) * iv;
        rres.y = (a0 * u.y + a1 * v.y) * iv;
        rres.z = (a0 * u.z + a1 * v.z) * iv;
        rres.w = (a0 * u.w + a1 * v.w) * iv;
        ob[e] = rres;
    }
}

// ---------------------------------------------------------------------------
// launch
// ---------------------------------------------------------------------------
extern "C" void kernel_launch(void* const* d_in, const int* in_sizes, int n_in,
                              void* d_out, int out_size)
{
    const float* x = (const float*)d_in[0];   // [B, T, C]
    const float* W = (const float*)d_in[1];   // [H, C]
    float* out = (float*)d_out;               // [B, T, H]

    float *kbuf = nullptr, *wt = nullptr, *part = nullptr, *stats = nullptr;
    cudaGetSymbolAddress((void**)&kbuf, g_kbuf);
    cudaGetSymbolAddress((void**)&wt, g_wt);
    cudaGetSymbolAddress((void**)&part, g_part);
    cudaGetSymbolAddress((void**)&stats, g_stats);

    cudaFuncSetAttribute(proj_kernel, cudaFuncAttributeMaxDynamicSharedMemorySize,
                         PROJ_SMEM_BYTES);
    cudaFuncSetAttribute(attn_kernel, cudaFuncAttributeMaxDynamicSharedMemorySize,
                         ATTN_SMEM_BYTES);

    wconv_kernel<<<HH, 256>>>(W, wt);

    proj_kernel<<<(BB * TT) / PROJ_M, 256, PROJ_SMEM_BYTES>>>(x, wt, kbuf);

    attn_kernel<<<48 * BB, 128, ATTN_SMEM_BYTES>>>(kbuf, out, part, stats);

    combine_kernel<<<BB * 16, 128>>>(part, stats, out);
}